// round 2
// baseline (speedup 1.0000x reference)
#include <cuda_runtime.h>
#include <cstddef>

#define MAXA 100000
#define DIM 512

// ---------------- scratch (static device globals; no allocation) ----------------
__device__ float g_msg [ (size_t)MAXA * DIM ];
__device__ float g_t0  [ (size_t)MAXA * DIM ];
__device__ float g_t1  [ (size_t)MAXA * DIM ];
__device__ float g_gath[ (size_t)MAXA * DIM ];
__device__ float g_bias[ (size_t)MAXA * DIM ];

// ---------------- generic fused SGEMM: C[M,512] = f( g(A[M,K]) @ W[K,512] + bias + add ) ----
// RELU_IN: relu applied to A elements on load. RELU_OUT: relu on output.
// bias: [512] or null. add: [M,512] or null (residual / precomputed bias map).
// zero_row0: force C[0,:] = 0.
template<bool RELU_IN, bool RELU_OUT>
__global__ void __launch_bounds__(256) sgemm512(
    const float* __restrict__ A, const float* __restrict__ W,
    const float* __restrict__ bias, const float* __restrict__ add,
    float* __restrict__ C, int M, int K, int zero_row0)
{
    __shared__ float As[16][132];   // [k][m], padded
    __shared__ float Bs[16][128];   // [k][n]

    const int tid  = threadIdx.x;
    const int row0 = blockIdx.y * 128;
    const int col0 = blockIdx.x * 128;
    const int tx = tid & 15;        // 0..15 col group
    const int ty = tid >> 4;        // 0..15 row group

    float acc[8][8];
    #pragma unroll
    for (int i = 0; i < 8; i++)
        #pragma unroll
        for (int j = 0; j < 8; j++) acc[i][j] = 0.f;

    const bool k_vec_ok = ((K & 3) == 0);   // rows 16B-aligned only if K%4==0

    for (int k0 = 0; k0 < K; k0 += 16) {
        // ---- load A tile (128 rows x 16 k), store transposed ----
        #pragma unroll
        for (int l = 0; l < 2; l++) {
            int f  = tid + l * 256;          // 0..511
            int r  = f >> 2;                 // 0..127
            int kq = (f & 3) * 4;            // 0,4,8,12
            int grow = row0 + r;
            float4 v = make_float4(0.f, 0.f, 0.f, 0.f);
            if (grow < M) {
                int k = k0 + kq;
                if (k_vec_ok && k + 3 < K) {
                    v = *(const float4*)(A + (size_t)grow * K + k);
                } else {
                    float t0v = (k + 0 < K) ? A[(size_t)grow * K + k + 0] : 0.f;
                    float t1v = (k + 1 < K) ? A[(size_t)grow * K + k + 1] : 0.f;
                    float t2v = (k + 2 < K) ? A[(size_t)grow * K + k + 2] : 0.f;
                    float t3v = (k + 3 < K) ? A[(size_t)grow * K + k + 3] : 0.f;
                    v = make_float4(t0v, t1v, t2v, t3v);
                }
            }
            if (RELU_IN) {
                v.x = fmaxf(v.x, 0.f); v.y = fmaxf(v.y, 0.f);
                v.z = fmaxf(v.z, 0.f); v.w = fmaxf(v.w, 0.f);
            }
            As[kq + 0][r] = v.x; As[kq + 1][r] = v.y;
            As[kq + 2][r] = v.z; As[kq + 3][r] = v.w;
        }
        // ---- load W tile (16 k-rows x 128 cols) ----
        #pragma unroll
        for (int l = 0; l < 2; l++) {
            int f  = tid + l * 256;
            int kr = f >> 5;                 // 0..15
            int n4 = (f & 31) * 4;           // 0..124
            float4 v = make_float4(0.f, 0.f, 0.f, 0.f);
            int k = k0 + kr;
            if (k < K) v = *(const float4*)(W + (size_t)k * DIM + col0 + n4);
            *(float4*)&Bs[kr][n4] = v;
        }
        __syncthreads();

        #pragma unroll
        for (int kk = 0; kk < 16; kk++) {
            float a[8], b[8];
            #pragma unroll
            for (int i = 0; i < 8; i++) a[i] = As[kk][ty * 8 + i];
            #pragma unroll
            for (int j = 0; j < 8; j++) b[j] = Bs[kk][tx * 8 + j];
            #pragma unroll
            for (int i = 0; i < 8; i++)
                #pragma unroll
                for (int j = 0; j < 8; j++)
                    acc[i][j] = fmaf(a[i], b[j], acc[i][j]);
        }
        __syncthreads();
    }

    // ---- epilogue ----
    #pragma unroll
    for (int i = 0; i < 8; i++) {
        int grow = row0 + ty * 8 + i;
        if (grow >= M) continue;
        #pragma unroll
        for (int j = 0; j < 8; j += 4) {
            int gc = col0 + tx * 8 + j;
            float4 r = make_float4(acc[i][j], acc[i][j+1], acc[i][j+2], acc[i][j+3]);
            if (bias) {
                const float4 bv = *(const float4*)(bias + gc);
                r.x += bv.x; r.y += bv.y; r.z += bv.z; r.w += bv.w;
            }
            if (add) {
                const float4 av = *(const float4*)(add + (size_t)grow * DIM + gc);
                r.x += av.x; r.y += av.y; r.z += av.z; r.w += av.w;
            }
            if (RELU_OUT) {
                r.x = fmaxf(r.x, 0.f); r.y = fmaxf(r.y, 0.f);
                r.z = fmaxf(r.z, 0.f); r.w = fmaxf(r.w, 0.f);
            }
            if (zero_row0 && grow == 0) r = make_float4(0.f, 0.f, 0.f, 0.f);
            *(float4*)(C + (size_t)grow * DIM + gc) = r;
        }
    }
}

// ---------------- neighbor gather-sum: dst[i,:] = sum_{j<6} src[a2a[i,j],:] ----------------
__global__ void gather_sum6(const float* __restrict__ src, const int* __restrict__ a2a,
                            float* __restrict__ dst)
{
    const int atom = blockIdx.x;
    const int t = threadIdx.x;                       // 128 threads, 4 floats each
    const int* idx = a2a + (size_t)atom * 6;
    float4 acc = make_float4(0.f, 0.f, 0.f, 0.f);
    #pragma unroll
    for (int j = 0; j < 6; j++) {
        const float4 v = *(const float4*)(src + (size_t)idx[j] * DIM + t * 4);
        acc.x += v.x; acc.y += v.y; acc.z += v.z; acc.w += v.w;
    }
    *(float4*)(dst + (size_t)atom * DIM + t * 4) = acc;
}

// ---------------- bond bias: dst[i,:] = relu(sum_j f_bonds[a2b[i,j],:]) @ Wb + b0 ----------
// Wb = Wh0_w rows 512..525 ([14,512]), b0 = Wh0_b. Constant over depths.
__global__ void bond_bias_kernel(const float* __restrict__ f_bonds, const int* __restrict__ a2b,
                                 const float* __restrict__ Wb, const float* __restrict__ b0,
                                 float* __restrict__ dst)
{
    const int atom = blockIdx.x;
    const int t = threadIdx.x;                       // 128 threads
    __shared__ float bs[14];
    if (t < 14) {
        const int* idx = a2b + (size_t)atom * 6;
        float s = 0.f;
        #pragma unroll
        for (int j = 0; j < 6; j++) s += f_bonds[(size_t)idx[j] * 14 + t];
        bs[t] = fmaxf(s, 0.f);
    }
    __syncthreads();
    #pragma unroll
    for (int r = 0; r < 4; r++) {
        int n = t + r * 128;
        float acc = b0[n];
        #pragma unroll
        for (int k = 0; k < 14; k++) acc = fmaf(bs[k], Wb[k * DIM + n], acc);
        dst[(size_t)atom * DIM + n] = acc;
    }
}

// ---------------- segment sum via atomics ----------------
__global__ void segment_atomic(const float* __restrict__ x, const int* __restrict__ mol_ids,
                               float* __restrict__ out, int n_mols)
{
    const int atom = blockIdx.x;
    const int mid = mol_ids[atom];
    if (mid < 0 || mid >= n_mols) return;            // padding atom dropped
    const int t = threadIdx.x;                        // 128 threads
    #pragma unroll
    for (int r = 0; r < 4; r++) {
        int n = t + r * 128;
        atomicAdd(out + (size_t)mid * DIM + n, x[(size_t)atom * DIM + n]);
    }
}

extern "C" void kernel_launch(void* const* d_in, const int* in_sizes, int n_in,
                              void* d_out, int out_size)
{
    const float* f_atoms = (const float*)d_in[0];
    const float* f_bonds = (const float*)d_in[1];
    const int*   a2a     = (const int*)d_in[2];
    const int*   a2b     = (const int*)d_in[3];
    const int*   mol_ids = (const int*)d_in[4];
    // Weights start after the graph tensors; n_mols may or may not appear as a tensor.
    const int base = n_in - 16;                      // 16 weight/bias tensors
    const float* W_i_w  = (const float*)d_in[base + 0];
    const float* W_i_b  = (const float*)d_in[base + 1];
    const float* Wh0_w  = (const float*)d_in[base + 2];
    const float* Wh0_b  = (const float*)d_in[base + 3];
    const float* Wh1_w  = (const float*)d_in[base + 4];
    const float* Wh1_b  = (const float*)d_in[base + 5];
    const float* Wh2_w  = (const float*)d_in[base + 6];
    const float* Wh2_b  = (const float*)d_in[base + 7];
    const float* Wah0_w = (const float*)d_in[base + 8];
    const float* Wah0_b = (const float*)d_in[base + 9];
    const float* Wah1_w = (const float*)d_in[base + 10];
    const float* Wah1_b = (const float*)d_in[base + 11];
    const float* Wah2_w = (const float*)d_in[base + 12];
    const float* Wah2_b = (const float*)d_in[base + 13];
    const float* W_o_w  = (const float*)d_in[base + 14];
    const float* W_o_b  = (const float*)d_in[base + 15];

    const int M      = in_sizes[0] / 133;            // atoms
    const int AFD    = 133;
    const int n_mols = out_size / DIM;

    float *p_msg, *p_t0, *p_t1, *p_gath, *p_bias;
    cudaGetSymbolAddress((void**)&p_msg,  g_msg);
    cudaGetSymbolAddress((void**)&p_t0,   g_t0);
    cudaGetSymbolAddress((void**)&p_t1,   g_t1);
    cudaGetSymbolAddress((void**)&p_gath, g_gath);
    cudaGetSymbolAddress((void**)&p_bias, g_bias);

    const dim3 gemm_grid(DIM / 128, (M + 127) / 128);
    const dim3 gemm_blk(256);

    cudaMemsetAsync(d_out, 0, (size_t)out_size * sizeof(float), 0);

    // depth-invariant bond bias: relu(sum f_bonds[a2b]) @ Wh0_w[512:526] + Wh0_b
    bond_bias_kernel<<<M, 128>>>(f_bonds, a2b, Wh0_w + (size_t)DIM * DIM, Wh0_b, p_bias);

    // msg = relu(f_atoms @ W_i + b), row0 zeroed   (self_msg == msg, see analysis)
    sgemm512<false, true><<<gemm_grid, gemm_blk>>>(f_atoms, W_i_w, W_i_b, nullptr, p_msg, M, AFD, 1);

    for (int d = 0; d < 4; d++) {
        gather_sum6<<<M, 128>>>(p_msg, a2a, p_gath);
        // t0 = relu(gath) @ Wh0_atom + bond_bias
        sgemm512<true, false><<<gemm_grid, gemm_blk>>>(p_gath, Wh0_w, nullptr, p_bias, p_t0, M, DIM, 0);
        // t1 = relu(t0) @ Wh1 + b1
        sgemm512<true, false><<<gemm_grid, gemm_blk>>>(p_t0, Wh1_w, Wh1_b, nullptr, p_t1, M, DIM, 0);
        // msg = relu(t1) @ Wh2 + b2 + msg, row0 zeroed (in-place residual)
        sgemm512<true, false><<<gemm_grid, gemm_blk>>>(p_t1, Wh2_w, Wh2_b, p_msg, p_msg, M, DIM, 1);
    }

    // a_message
    gather_sum6<<<M, 128>>>(p_msg, a2a, p_gath);

    // cc chain
    sgemm512<false, true><<<gemm_grid, gemm_blk>>>(f_atoms, Wah0_w, Wah0_b, nullptr, p_t0, M, AFD, 0);
    sgemm512<false, true><<<gemm_grid, gemm_blk>>>(p_t0, Wah1_w, Wah1_b, nullptr, p_t1, M, DIM, 0);
    sgemm512<false, true><<<gemm_grid, gemm_blk>>>(p_t1, Wah2_w, Wah2_b, nullptr, p_t0, M, DIM, 0);

    // out = relu(cc @ Wo_top + a_message @ Wo_bot + b)
    sgemm512<false, false><<<gemm_grid, gemm_blk>>>(p_t0, W_o_w, W_o_b, nullptr, p_t1, M, DIM, 0);
    sgemm512<false, true ><<<gemm_grid, gemm_blk>>>(p_gath, W_o_w + (size_t)DIM * DIM, nullptr, p_t1, p_t0, M, DIM, 0);

    // per-molecule pooling
    segment_atomic<<<M, 128>>>(p_t0, mol_ids, (float*)d_out, n_mols);
}

// round 4
// speedup vs baseline: 1.2921x; 1.2921x over previous
#include <cuda_runtime.h>
#include <cuda_bf16.h>
#include <cstdint>
#include <cstddef>

#define DIM 512
#define MAXA 100000

// ---------------- scratch (static device globals; no allocation) ----------------
__device__ float g_msg [(size_t)MAXA * DIM];
__device__ float g_t0  [(size_t)MAXA * DIM];
__device__ float g_t1  [(size_t)MAXA * DIM];
__device__ float g_gath[(size_t)MAXA * DIM];
__device__ float g_bias[(size_t)MAXA * DIM];
// transposed + bf16-split weight planes: hi[512][Kp] then lo[512][Kp] per GEMM
__device__ __align__(16) __nv_bfloat16 g_wt[4063232];

// ---------------- helpers ----------------
__device__ __forceinline__ uint32_t s2u(const void* p) {
    uint32_t a;
    asm("{ .reg .u64 t; cvta.to.shared.u64 t, %1; cvt.u32.u64 %0, t; }" : "=r"(a) : "l"(p));
    return a;
}

#define CP16(dst, src) \
    asm volatile("cp.async.cg.shared.global [%0], [%1], 16;" :: "r"(dst), "l"(src) : "memory")
#define CP_COMMIT() asm volatile("cp.async.commit_group;" ::: "memory")
#define CP_WAIT0()  asm volatile("cp.async.wait_group 0;" ::: "memory")

#define LDSM4(r, addr) \
    asm volatile("ldmatrix.sync.aligned.m8n8.x4.shared.b16 {%0,%1,%2,%3}, [%4];" \
        : "=r"((r)[0]), "=r"((r)[1]), "=r"((r)[2]), "=r"((r)[3]) : "r"(addr))

#define MMA16816(d, a, b0, b1) \
    asm volatile("mma.sync.aligned.m16n8k16.row.col.f32.bf16.bf16.f32 " \
        "{%0,%1,%2,%3}, {%4,%5,%6,%7}, {%8,%9}, {%0,%1,%2,%3};" \
        : "+f"((d)[0]), "+f"((d)[1]), "+f"((d)[2]), "+f"((d)[3]) \
        : "r"((a)[0]), "r"((a)[1]), "r"((a)[2]), "r"((a)[3]), "r"(b0), "r"(b1))

__device__ __forceinline__ void split2(float a0, float a1, uint32_t& h, uint32_t& l) {
    __nv_bfloat16 h0 = __float2bfloat16(a0);
    __nv_bfloat16 h1 = __float2bfloat16(a1);
    __nv_bfloat16 b0 = __float2bfloat16(a0 - __bfloat162float(h0));
    __nv_bfloat16 b1 = __float2bfloat16(a1 - __bfloat162float(h1));
    h = (uint32_t)__bfloat16_as_ushort(h0) | ((uint32_t)__bfloat16_as_ushort(h1) << 16);
    l = (uint32_t)__bfloat16_as_ushort(b0) | ((uint32_t)__bfloat16_as_ushort(b1) << 16);
}

// ---------------- weight prep: W[K,512] fp32 -> Wt hi/lo [512][Kp] bf16 ----------------
__global__ void prep_weight(const float* __restrict__ W, __nv_bfloat16* __restrict__ hi,
                            int Kreal, int Kp) {
    __nv_bfloat16* lo = hi + (size_t)512 * Kp;
    int total = 512 * Kp;
    for (int idx = blockIdx.x * blockDim.x + threadIdx.x; idx < total;
         idx += gridDim.x * blockDim.x) {
        int n = idx / Kp, k = idx - n * Kp;
        float v = (k < Kreal) ? W[(size_t)k * 512 + n] : 0.f;
        __nv_bfloat16 h = __float2bfloat16(v);
        hi[idx] = h;
        lo[idx] = __float2bfloat16(v - __bfloat162float(h));
    }
}

// ---------------- HMMA GEMM: C[M,512] = f(g(A[M,K]) @ W[K,512] + bias + add) --------------
// grid (4, ceil(M/128)), 256 threads, dyn smem 73728 B.
// smem: As_hi@0, As_lo@18432, Bs_hi@36864, Bs_lo@55296  (each [128 rows][144 B], 64 bf16 + pad)
template<bool RELU_IN, bool RELU_OUT, bool K_ALIGNED>
__global__ void __launch_bounds__(256, 2) gemm_mma(
    const float* __restrict__ A, const __nv_bfloat16* __restrict__ Whi,
    const float* __restrict__ bias, const float* __restrict__ add,
    float* __restrict__ C, int M, int K, int Kp, int zero_row0)
{
    extern __shared__ __align__(16) char smem[];
    const uint32_t sb = s2u(smem);
    const int AS_HI = 0, AS_LO = 18432, BS_HI = 36864, BS_LO = 55296;
    const int PLANE = 18432;                  // hi->lo plane offset (same for A and B)

    const __nv_bfloat16* Wlo = Whi + (size_t)512 * Kp;
    const int tid = threadIdx.x, lane = tid & 31, wid = tid >> 5;
    const int wm = wid >> 1, wn = wid & 1;    // warp grid 4x2, warp tile 32M x 64N
    const int row0 = blockIdx.y * 128, col0 = blockIdx.x * 128;
    const int nch = Kp >> 6;

    float acc[2][8][4];
    #pragma unroll
    for (int i = 0; i < 2; i++)
        #pragma unroll
        for (int j = 0; j < 8; j++)
            #pragma unroll
            for (int q = 0; q < 4; q++) acc[i][j][q] = 0.f;

    // loader coords: 2 threads per row, 32 k-elems each
    const int lr = tid >> 1, lk = (tid & 1) * 32;
    const int grow = row0 + lr;

    // ldmatrix source addresses (constant parts)
    const uint32_t a_addr0 = sb + AS_HI + (uint32_t)(wm * 32 + (lane & 15)) * 144
                             + (uint32_t)(lane >> 4) * 16;
    const uint32_t b_addr0 = sb + BS_HI
                             + (uint32_t)(wn * 64 + (lane & 7) + ((lane >> 4) & 1) * 8) * 144
                             + (uint32_t)((lane >> 3) & 1) * 16;

    for (int c = 0; c < nch; c++) {
        if (c) __syncthreads();

        // ---- B tiles via cp.async (both planes), 64 B per thread per plane ----
        {
            const __nv_bfloat16* bh = Whi + (size_t)(col0 + lr) * Kp + c * 64 + lk;
            const __nv_bfloat16* bl = Wlo + (size_t)(col0 + lr) * Kp + c * 64 + lk;
            uint32_t d0 = sb + BS_HI + (uint32_t)lr * 144 + lk * 2;
            uint32_t d1 = d0 + PLANE;
            CP16(d0,      bh);      CP16(d0 + 16, bh + 8);
            CP16(d0 + 32, bh + 16); CP16(d0 + 48, bh + 24);
            CP16(d1,      bl);      CP16(d1 + 16, bl + 8);
            CP16(d1 + 32, bl + 16); CP16(d1 + 48, bl + 24);
            CP_COMMIT();
        }

        // ---- A tile: fp32 -> bf16 hi/lo, 8-float groups ----
        {
            char* arow = smem + AS_HI + (size_t)lr * 144 + lk * 2;
            #pragma unroll
            for (int g = 0; g < 4; g++) {
                float f[8];
                if (grow < M) {
                    if (K_ALIGNED) {
                        const float4* ap = (const float4*)(A + (size_t)grow * K + c * 64 + lk + g * 8);
                        float4 v0 = ap[0], v1 = ap[1];
                        f[0] = v0.x; f[1] = v0.y; f[2] = v0.z; f[3] = v0.w;
                        f[4] = v1.x; f[5] = v1.y; f[6] = v1.z; f[7] = v1.w;
                    } else {
                        #pragma unroll
                        for (int j = 0; j < 8; j++) {
                            int k = c * 64 + lk + g * 8 + j;
                            f[j] = (k < K) ? A[(size_t)grow * K + k] : 0.f;
                        }
                    }
                } else {
                    #pragma unroll
                    for (int j = 0; j < 8; j++) f[j] = 0.f;
                }
                if (RELU_IN) {
                    #pragma unroll
                    for (int j = 0; j < 8; j++) f[j] = fmaxf(f[j], 0.f);
                }
                uint32_t h[4], l[4];
                #pragma unroll
                for (int p = 0; p < 4; p++) split2(f[2 * p], f[2 * p + 1], h[p], l[p]);
                *(uint4*)(arow + g * 16)         = make_uint4(h[0], h[1], h[2], h[3]);
                *(uint4*)(arow + PLANE + g * 16) = make_uint4(l[0], l[1], l[2], l[3]);
            }
        }

        CP_WAIT0();
        __syncthreads();

        // ---- compute: 4 k16 steps ----
        #pragma unroll
        for (int ks = 0; ks < 4; ks++) {
            uint32_t ah[2][4], al[2][4];
            #pragma unroll
            for (int mt = 0; mt < 2; mt++) {
                uint32_t aa = a_addr0 + mt * 16 * 144 + ks * 32;
                LDSM4(ah[mt], aa);
                LDSM4(al[mt], aa + PLANE);
            }
            #pragma unroll
            for (int ntp = 0; ntp < 4; ntp++) {
                uint32_t bh[4], bl[4];
                uint32_t ba = b_addr0 + ntp * 16 * 144 + ks * 32;
                LDSM4(bh, ba);
                LDSM4(bl, ba + PLANE);
                #pragma unroll
                for (int h = 0; h < 2; h++) {
                    const int nt = ntp * 2 + h;
                    #pragma unroll
                    for (int mt = 0; mt < 2; mt++) {
                        MMA16816(acc[mt][nt], ah[mt], bh[2 * h], bh[2 * h + 1]);
                        MMA16816(acc[mt][nt], ah[mt], bl[2 * h], bl[2 * h + 1]);
                        MMA16816(acc[mt][nt], al[mt], bh[2 * h], bh[2 * h + 1]);
                    }
                }
            }
        }
    }

    // ---- epilogue ----
    const int g = lane >> 2, tg = lane & 3;
    #pragma unroll
    for (int mt = 0; mt < 2; mt++) {
        #pragma unroll
        for (int nt = 0; nt < 8; nt++) {
            const int col = col0 + wn * 64 + nt * 8 + tg * 2;
            #pragma unroll
            for (int half = 0; half < 2; half++) {
                const int row = row0 + wm * 32 + mt * 16 + g + half * 8;
                if (row >= M) continue;
                float v0 = acc[mt][nt][half * 2 + 0];
                float v1 = acc[mt][nt][half * 2 + 1];
                if (bias) {
                    const float2 bv = *(const float2*)(bias + col);
                    v0 += bv.x; v1 += bv.y;
                }
                if (add) {
                    const float2 av = *(const float2*)(add + (size_t)row * DIM + col);
                    v0 += av.x; v1 += av.y;
                }
                if (RELU_OUT) { v0 = fmaxf(v0, 0.f); v1 = fmaxf(v1, 0.f); }
                if (zero_row0 && row == 0) { v0 = 0.f; v1 = 0.f; }
                *(float2*)(C + (size_t)row * DIM + col) = make_float2(v0, v1);
            }
        }
    }
}

// ---------------- neighbor gather-sum ----------------
__global__ void gather_sum6(const float* __restrict__ src, const int* __restrict__ a2a,
                            float* __restrict__ dst)
{
    const int atom = blockIdx.x;
    const int t = threadIdx.x;
    const int* idx = a2a + (size_t)atom * 6;
    float4 acc = make_float4(0.f, 0.f, 0.f, 0.f);
    #pragma unroll
    for (int j = 0; j < 6; j++) {
        const float4 v = *(const float4*)(src + (size_t)idx[j] * DIM + t * 4);
        acc.x += v.x; acc.y += v.y; acc.z += v.z; acc.w += v.w;
    }
    *(float4*)(dst + (size_t)atom * DIM + t * 4) = acc;
}

// ---------------- bond bias ----------------
__global__ void bond_bias_kernel(const float* __restrict__ f_bonds, const int* __restrict__ a2b,
                                 const float* __restrict__ Wb, const float* __restrict__ b0,
                                 float* __restrict__ dst)
{
    const int atom = blockIdx.x;
    const int t = threadIdx.x;
    __shared__ float bs[14];
    if (t < 14) {
        const int* idx = a2b + (size_t)atom * 6;
        float s = 0.f;
        #pragma unroll
        for (int j = 0; j < 6; j++) s += f_bonds[(size_t)idx[j] * 14 + t];
        bs[t] = fmaxf(s, 0.f);
    }
    __syncthreads();
    #pragma unroll
    for (int rr = 0; rr < 4; rr++) {
        int n = t + rr * 128;
        float acc = b0[n];
        #pragma unroll
        for (int k = 0; k < 14; k++) acc = fmaf(bs[k], Wb[k * DIM + n], acc);
        dst[(size_t)atom * DIM + n] = acc;
    }
}

// ---------------- segment sum via atomics ----------------
__global__ void segment_atomic(const float* __restrict__ x, const int* __restrict__ mol_ids,
                               float* __restrict__ out, int n_mols)
{
    const int atom = blockIdx.x;
    const int mid = mol_ids[atom];
    if (mid < 0 || mid >= n_mols) return;
    const int t = threadIdx.x;
    #pragma unroll
    for (int rr = 0; rr < 4; rr++) {
        int n = t + rr * 128;
        atomicAdd(out + (size_t)mid * DIM + n, x[(size_t)atom * DIM + n]);
    }
}

extern "C" void kernel_launch(void* const* d_in, const int* in_sizes, int n_in,
                              void* d_out, int out_size)
{
    const float* f_atoms = (const float*)d_in[0];
    const float* f_bonds = (const float*)d_in[1];
    const int*   a2a     = (const int*)d_in[2];
    const int*   a2b     = (const int*)d_in[3];
    const int*   mol_ids = (const int*)d_in[4];
    const int base = n_in - 16;
    const float* W_i_w  = (const float*)d_in[base + 0];
    const float* W_i_b  = (const float*)d_in[base + 1];
    const float* Wh0_w  = (const float*)d_in[base + 2];
    const float* Wh0_b  = (const float*)d_in[base + 3];
    const float* Wh1_w  = (const float*)d_in[base + 4];
    const float* Wh1_b  = (const float*)d_in[base + 5];
    const float* Wh2_w  = (const float*)d_in[base + 6];
    const float* Wh2_b  = (const float*)d_in[base + 7];
    const float* Wah0_w = (const float*)d_in[base + 8];
    const float* Wah0_b = (const float*)d_in[base + 9];
    const float* Wah1_w = (const float*)d_in[base + 10];
    const float* Wah1_b = (const float*)d_in[base + 11];
    const float* Wah2_w = (const float*)d_in[base + 12];
    const float* Wah2_b = (const float*)d_in[base + 13];
    const float* W_o_w  = (const float*)d_in[base + 14];
    const float* W_o_b  = (const float*)d_in[base + 15];

    const int M      = in_sizes[0] / 133;
    const int n_mols = out_size / DIM;

    float *p_msg, *p_t0, *p_t1, *p_gath, *p_bias;
    __nv_bfloat16* p_wt;
    cudaGetSymbolAddress((void**)&p_msg,  g_msg);
    cudaGetSymbolAddress((void**)&p_t0,   g_t0);
    cudaGetSymbolAddress((void**)&p_t1,   g_t1);
    cudaGetSymbolAddress((void**)&p_gath, g_gath);
    cudaGetSymbolAddress((void**)&p_bias, g_bias);
    cudaGetSymbolAddress((void**)&p_wt,   g_wt);

    // weight plane offsets in bf16 elements (hi plane; lo = hi + 512*Kp)
    const size_t OFF_WI   = 0;         // Kp=192: 2*512*192 = 196608
    const size_t OFF_WAH0 = 196608;    // Kp=192
    const size_t OFF_WH0  = 393216;    // Kp=512: 2*512*512 = 524288 each
    const size_t OFF_WH1  = 917504;
    const size_t OFF_WH2  = 1441792;
    const size_t OFF_WAH1 = 1966080;
    const size_t OFF_WAH2 = 2490368;
    const size_t OFF_WOT  = 3014656;
    const size_t OFF_WOB  = 3538944;

    const int SMEM_BYTES = 73728;
    cudaFuncSetAttribute(gemm_mma<false, true,  false>, cudaFuncAttributeMaxDynamicSharedMemorySize, SMEM_BYTES);
    cudaFuncSetAttribute(gemm_mma<true,  false, true >, cudaFuncAttributeMaxDynamicSharedMemorySize, SMEM_BYTES);
    cudaFuncSetAttribute(gemm_mma<false, true,  true >, cudaFuncAttributeMaxDynamicSharedMemorySize, SMEM_BYTES);
    cudaFuncSetAttribute(gemm_mma<false, false, true >, cudaFuncAttributeMaxDynamicSharedMemorySize, SMEM_BYTES);

    // ---- weight prep ----
    prep_weight<<<256, 256>>>(W_i_w,  p_wt + OFF_WI,   133, 192);
    prep_weight<<<256, 256>>>(Wah0_w, p_wt + OFF_WAH0, 133, 192);
    prep_weight<<<256, 256>>>(Wh0_w,  p_wt + OFF_WH0,  512, 512);
    prep_weight<<<256, 256>>>(Wh1_w,  p_wt + OFF_WH1,  512, 512);
    prep_weight<<<256, 256>>>(Wh2_w,  p_wt + OFF_WH2,  512, 512);
    prep_weight<<<256, 256>>>(Wah1_w, p_wt + OFF_WAH1, 512, 512);
    prep_weight<<<256, 256>>>(Wah2_w, p_wt + OFF_WAH2, 512, 512);
    prep_weight<<<256, 256>>>(W_o_w,                     p_wt + OFF_WOT, 512, 512);
    prep_weight<<<256, 256>>>(W_o_w + (size_t)DIM * DIM, p_wt + OFF_WOB, 512, 512);

    cudaMemsetAsync(d_out, 0, (size_t)out_size * sizeof(float), 0);

    bond_bias_kernel<<<M, 128>>>(f_bonds, a2b, Wh0_w + (size_t)DIM * DIM, Wh0_b, p_bias);

    const dim3 gg(4, (M + 127) / 128);

    // msg = relu(f_atoms @ W_i + b_i), row0 zeroed
    gemm_mma<false, true, false><<<gg, 256, SMEM_BYTES>>>(
        f_atoms, p_wt + OFF_WI, W_i_b, nullptr, p_msg, M, 133, 192, 1);

    for (int d = 0; d < 4; d++) {
        gather_sum6<<<M, 128>>>(p_msg, a2a, p_gath);
        gemm_mma<true, false, true><<<gg, 256, SMEM_BYTES>>>(
            p_gath, p_wt + OFF_WH0, nullptr, p_bias, p_t0, M, 512, 512, 0);
        gemm_mma<true, false, true><<<gg, 256, SMEM_BYTES>>>(
            p_t0, p_wt + OFF_WH1, Wh1_b, nullptr, p_t1, M, 512, 512, 0);
        gemm_mma<true, false, true><<<gg, 256, SMEM_BYTES>>>(
            p_t1, p_wt + OFF_WH2, Wh2_b, p_msg, p_msg, M, 512, 512, 1);
    }

    gather_sum6<<<M, 128>>>(p_msg, a2a, p_gath);

    // cc chain
    gemm_mma<false, true, false><<<gg, 256, SMEM_BYTES>>>(
        f_atoms, p_wt + OFF_WAH0, Wah0_b, nullptr, p_t0, M, 133, 192, 0);
    gemm_mma<false, true, true><<<gg, 256, SMEM_BYTES>>>(
        p_t0, p_wt + OFF_WAH1, Wah1_b, nullptr, p_t1, M, 512, 512, 0);
    gemm_mma<false, true, true><<<gg, 256, SMEM_BYTES>>>(
        p_t1, p_wt + OFF_WAH2, Wah2_b, nullptr, p_t0, M, 512, 512, 0);

    // out = relu(cc @ Wo_top + a_message @ Wo_bot + b_o)
    gemm_mma<false, false, true><<<gg, 256, SMEM_BYTES>>>(
        p_t0, p_wt + OFF_WOT, W_o_b, nullptr, p_t1, M, 512, 512, 0);
    gemm_mma<false, true, true><<<gg, 256, SMEM_BYTES>>>(
        p_gath, p_wt + OFF_WOB, nullptr, p_t1, p_t0, M, 512, 512, 0);

    segment_atomic<<<M, 128>>>(p_t0, mol_ids, (float*)d_out, n_mols);
}

// round 6
// speedup vs baseline: 1.7128x; 1.3256x over previous
#include <cuda_runtime.h>
#include <cuda_bf16.h>
#include <cstdint>
#include <cstddef>

#define DIM 512
#define MAXA 100000

// ---------------- scratch (static device globals; no allocation) ----------------
__device__ float g_msg [(size_t)MAXA * DIM];
__device__ float g_t0  [(size_t)MAXA * DIM];
__device__ float g_t1  [(size_t)MAXA * DIM];
__device__ float g_gath[(size_t)MAXA * DIM];
__device__ float g_bias[(size_t)MAXA * DIM];
// transposed + bf16-split weight planes: hi[512][Kp] then lo[512][Kp] per GEMM
__device__ __align__(16) __nv_bfloat16 g_wt[4063232];

// ---------------- helpers ----------------
__device__ __forceinline__ uint32_t s2u(const void* p) {
    uint32_t a;
    asm("{ .reg .u64 t; cvta.to.shared.u64 t, %1; cvt.u32.u64 %0, t; }" : "=r"(a) : "l"(p));
    return a;
}

#define CP16(dst, src) \
    asm volatile("cp.async.cg.shared.global [%0], [%1], 16;" :: "r"(dst), "l"(src) : "memory")
#define CP_COMMIT() asm volatile("cp.async.commit_group;" ::: "memory")
#define CP_WAIT1()  asm volatile("cp.async.wait_group 1;" ::: "memory")

#define LDSM4(r, addr) \
    asm volatile("ldmatrix.sync.aligned.m8n8.x4.shared.b16 {%0,%1,%2,%3}, [%4];" \
        : "=r"((r)[0]), "=r"((r)[1]), "=r"((r)[2]), "=r"((r)[3]) : "r"(addr))

#define MMA16816(d, a, b0, b1) \
    asm volatile("mma.sync.aligned.m16n8k16.row.col.f32.bf16.bf16.f32 " \
        "{%0,%1,%2,%3}, {%4,%5,%6,%7}, {%8,%9}, {%0,%1,%2,%3};" \
        : "+f"((d)[0]), "+f"((d)[1]), "+f"((d)[2]), "+f"((d)[3]) \
        : "r"((a)[0]), "r"((a)[1]), "r"((a)[2]), "r"((a)[3]), "r"(b0), "r"(b1))

__device__ __forceinline__ void split2(float a0, float a1, uint32_t& h, uint32_t& l) {
    __nv_bfloat16 h0 = __float2bfloat16(a0);
    __nv_bfloat16 h1 = __float2bfloat16(a1);
    __nv_bfloat16 b0 = __float2bfloat16(a0 - __bfloat162float(h0));
    __nv_bfloat16 b1 = __float2bfloat16(a1 - __bfloat162float(h1));
    h = (uint32_t)__bfloat16_as_ushort(h0) | ((uint32_t)__bfloat16_as_ushort(h1) << 16);
    l = (uint32_t)__bfloat16_as_ushort(b0) | ((uint32_t)__bfloat16_as_ushort(b1) << 16);
}

// ---------------- weight prep: W[K,512] fp32 -> Wt hi/lo [512][Kp] bf16 ----------------
__global__ void prep_weight(const float* __restrict__ W, __nv_bfloat16* __restrict__ hi,
                            int Kreal, int Kp) {
    __nv_bfloat16* lo = hi + (size_t)512 * Kp;
    int total = 512 * Kp;
    for (int idx = blockIdx.x * blockDim.x + threadIdx.x; idx < total;
         idx += gridDim.x * blockDim.x) {
        int n = idx / Kp, k = idx - n * Kp;
        float v = (k < Kreal) ? W[(size_t)k * 512 + n] : 0.f;
        __nv_bfloat16 h = __float2bfloat16(v);
        hi[idx] = h;
        lo[idx] = __float2bfloat16(v - __bfloat162float(h));
    }
}

// ---------------- HMMA GEMM: C[M,512] = f(g(A[M,K]) @ W[K,512] + bias + add) --------------
// grid (4, ceil(M/128)), 256 threads, dyn smem 110592 B, 2 CTAs/SM.
// smem: As_hi@0, As_lo@18432 (single-buffered),
//       B double-buffered @36864 + buf*36864 (hi at +0, lo at +18432)
// rows are 144 B (64 bf16 + 16 B pad) -> conflict-free ldmatrix
template<bool RELU_IN, bool RELU_OUT, bool K_ALIGNED>
__global__ void __launch_bounds__(256, 2) gemm_mma(
    const float* __restrict__ A, const __nv_bfloat16* __restrict__ Whi,
    const float* __restrict__ bias, const float* __restrict__ add,
    float* __restrict__ C, int M, int K, int Kp, int zero_row0)
{
    extern __shared__ __align__(16) char smem[];
    const uint32_t sb = s2u(smem);
    const int PLANE = 18432;                  // hi->lo plane offset (A and B)
    const int BS0 = 36864, BSTRIDE = 36864;   // B buffer base / stride

    const __nv_bfloat16* Wlo = Whi + (size_t)512 * Kp;
    const int tid = threadIdx.x, lane = tid & 31, wid = tid >> 5;
    const int wm = wid >> 1, wn = wid & 1;    // warp grid 4x2, warp tile 32M x 64N
    const int row0 = blockIdx.y * 128, col0 = blockIdx.x * 128;
    const int nch = Kp >> 6;

    float acc[2][8][4];
    #pragma unroll
    for (int i = 0; i < 2; i++)
        #pragma unroll
        for (int j = 0; j < 8; j++)
            #pragma unroll
            for (int q = 0; q < 4; q++) acc[i][j][q] = 0.f;

    // loader coords: 2 threads per row, 32 k-elems each
    const int lr = tid >> 1, lk = (tid & 1) * 32;
    const int grow = row0 + lr;

    // ldmatrix source addresses (constant parts)
    const uint32_t a_addr0 = sb + (uint32_t)(wm * 32 + (lane & 15)) * 144
                             + (uint32_t)(lane >> 4) * 16;
    const uint32_t b_row_off = (uint32_t)(wn * 64 + (lane & 7) + ((lane >> 4) & 1) * 8) * 144
                               + (uint32_t)((lane >> 3) & 1) * 16;

    const uint32_t b_dst_off = (uint32_t)lr * 144 + (uint32_t)lk * 2;
    const __nv_bfloat16* bh_base = Whi + (size_t)(col0 + lr) * Kp + lk;
    const __nv_bfloat16* bl_base = Wlo + (size_t)(col0 + lr) * Kp + lk;

    // ---- prologue: issue B chunk 0 into buffer 0 ----
    {
        const __nv_bfloat16* bh = bh_base;          // c = 0
        const __nv_bfloat16* bl = bl_base;
        uint32_t d0 = sb + BS0 + b_dst_off;
        uint32_t d1 = d0 + PLANE;
        CP16(d0,      bh);      CP16(d0 + 16, bh + 8);
        CP16(d0 + 32, bh + 16); CP16(d0 + 48, bh + 24);
        CP16(d1,      bl);      CP16(d1 + 16, bl + 8);
        CP16(d1 + 32, bl + 16); CP16(d1 + 48, bl + 24);
        CP_COMMIT();
    }

    for (int c = 0; c < nch; c++) {
        // ---- A tile chunk c: fp32 -> bf16 hi/lo (single buffer; prev compute synced) ----
        {
            char* arow = smem + (size_t)lr * 144 + lk * 2;
            #pragma unroll
            for (int g = 0; g < 4; g++) {
                float f[8];
                if (grow < M) {
                    if (K_ALIGNED) {
                        const float4* ap = (const float4*)(A + (size_t)grow * K + c * 64 + lk + g * 8);
                        float4 v0 = ap[0], v1 = ap[1];
                        f[0] = v0.x; f[1] = v0.y; f[2] = v0.z; f[3] = v0.w;
                        f[4] = v1.x; f[5] = v1.y; f[6] = v1.z; f[7] = v1.w;
                    } else {
                        #pragma unroll
                        for (int j = 0; j < 8; j++) {
                            int k = c * 64 + lk + g * 8 + j;
                            f[j] = (k < K) ? A[(size_t)grow * K + k] : 0.f;
                        }
                    }
                } else {
                    #pragma unroll
                    for (int j = 0; j < 8; j++) f[j] = 0.f;
                }
                if (RELU_IN) {
                    #pragma unroll
                    for (int j = 0; j < 8; j++) f[j] = fmaxf(f[j], 0.f);
                }
                uint32_t h[4], l[4];
                #pragma unroll
                for (int p = 0; p < 4; p++) split2(f[2 * p], f[2 * p + 1], h[p], l[p]);
                *(uint4*)(arow + g * 16)         = make_uint4(h[0], h[1], h[2], h[3]);
                *(uint4*)(arow + PLANE + g * 16) = make_uint4(l[0], l[1], l[2], l[3]);
            }
        }

        // ---- prefetch B chunk c+1 into alternate buffer ----
        if (c + 1 < nch) {
            const __nv_bfloat16* bh = bh_base + (c + 1) * 64;
            const __nv_bfloat16* bl = bl_base + (c + 1) * 64;
            uint32_t d0 = sb + BS0 + ((c + 1) & 1) * BSTRIDE + b_dst_off;
            uint32_t d1 = d0 + PLANE;
            CP16(d0,      bh);      CP16(d0 + 16, bh + 8);
            CP16(d0 + 32, bh + 16); CP16(d0 + 48, bh + 24);
            CP16(d1,      bl);      CP16(d1 + 16, bl + 8);
            CP16(d1 + 32, bl + 16); CP16(d1 + 48, bl + 24);
        }
        CP_COMMIT();
        CP_WAIT1();               // B chunk c resident (newest group may be in flight)
        __syncthreads();

        // ---- compute chunk c: 4 k16 steps ----
        const uint32_t b_addr0 = sb + BS0 + (uint32_t)((c & 1) * BSTRIDE) + b_row_off;
        #pragma unroll
        for (int ks = 0; ks < 4; ks++) {
            uint32_t ah[2][4], al[2][4];
            #pragma unroll
            for (int mt = 0; mt < 2; mt++) {
                uint32_t aa = a_addr0 + mt * 16 * 144 + ks * 32;
                LDSM4(ah[mt], aa);
                LDSM4(al[mt], aa + PLANE);
            }
            #pragma unroll
            for (int ntp = 0; ntp < 4; ntp++) {
                uint32_t bh[4], bl[4];
                uint32_t ba = b_addr0 + ntp * 16 * 144 + ks * 32;
                LDSM4(bh, ba);
                LDSM4(bl, ba + PLANE);
                #pragma unroll
                for (int h = 0; h < 2; h++) {
                    const int nt = ntp * 2 + h;
                    #pragma unroll
                    for (int mt = 0; mt < 2; mt++) {
                        MMA16816(acc[mt][nt], ah[mt], bh[2 * h], bh[2 * h + 1]);
                        MMA16816(acc[mt][nt], ah[mt], bl[2 * h], bl[2 * h + 1]);
                        MMA16816(acc[mt][nt], al[mt], bh[2 * h], bh[2 * h + 1]);
                    }
                }
            }
        }
        __syncthreads();          // A buffer free for next chunk
    }

    // ---- epilogue ----
    const int g = lane >> 2, tg = lane & 3;
    #pragma unroll
    for (int mt = 0; mt < 2; mt++) {
        #pragma unroll
        for (int nt = 0; nt < 8; nt++) {
            const int col = col0 + wn * 64 + nt * 8 + tg * 2;
            #pragma unroll
            for (int half = 0; half < 2; half++) {
                const int row = row0 + wm * 32 + mt * 16 + g + half * 8;
                if (row >= M) continue;
                float v0 = acc[mt][nt][half * 2 + 0];
                float v1 = acc[mt][nt][half * 2 + 1];
                if (bias) {
                    const float2 bv = *(const float2*)(bias + col);
                    v0 += bv.x; v1 += bv.y;
                }
                if (add) {
                    const float2 av = *(const float2*)(add + (size_t)row * DIM + col);
                    v0 += av.x; v1 += av.y;
                }
                if (RELU_OUT) { v0 = fmaxf(v0, 0.f); v1 = fmaxf(v1, 0.f); }
                if (zero_row0 && row == 0) { v0 = 0.f; v1 = 0.f; }
                *(float2*)(C + (size_t)row * DIM + col) = make_float2(v0, v1);
            }
        }
    }
}

// ---------------- neighbor gather-sum ----------------
__global__ void gather_sum6(const float* __restrict__ src, const int* __restrict__ a2a,
                            float* __restrict__ dst)
{
    const int atom = blockIdx.x;
    const int t = threadIdx.x;
    const int* idx = a2a + (size_t)atom * 6;
    float4 acc = make_float4(0.f, 0.f, 0.f, 0.f);
    #pragma unroll
    for (int j = 0; j < 6; j++) {
        const float4 v = *(const float4*)(src + (size_t)idx[j] * DIM + t * 4);
        acc.x += v.x; acc.y += v.y; acc.z += v.z; acc.w += v.w;
    }
    *(float4*)(dst + (size_t)atom * DIM + t * 4) = acc;
}

// ---------------- bond bias ----------------
__global__ void bond_bias_kernel(const float* __restrict__ f_bonds, const int* __restrict__ a2b,
                                 const float* __restrict__ Wb, const float* __restrict__ b0,
                                 float* __restrict__ dst)
{
    const int atom = blockIdx.x;
    const int t = threadIdx.x;
    __shared__ float bs[14];
    if (t < 14) {
        const int* idx = a2b + (size_t)atom * 6;
        float s = 0.f;
        #pragma unroll
        for (int j = 0; j < 6; j++) s += f_bonds[(size_t)idx[j] * 14 + t];
        bs[t] = fmaxf(s, 0.f);
    }
    __syncthreads();
    #pragma unroll
    for (int rr = 0; rr < 4; rr++) {
        int n = t + rr * 128;
        float acc = b0[n];
        #pragma unroll
        for (int k = 0; k < 14; k++) acc = fmaf(bs[k], Wb[k * DIM + n], acc);
        dst[(size_t)atom * DIM + n] = acc;
    }
}

// ---------------- segment sum via atomics ----------------
__global__ void segment_atomic(const float* __restrict__ x, const int* __restrict__ mol_ids,
                               float* __restrict__ out, int n_mols)
{
    const int atom = blockIdx.x;
    const int mid = mol_ids[atom];
    if (mid < 0 || mid >= n_mols) return;
    const int t = threadIdx.x;
    #pragma unroll
    for (int rr = 0; rr < 4; rr++) {
        int n = t + rr * 128;
        atomicAdd(out + (size_t)mid * DIM + n, x[(size_t)atom * DIM + n]);
    }
}

extern "C" void kernel_launch(void* const* d_in, const int* in_sizes, int n_in,
                              void* d_out, int out_size)
{
    const float* f_atoms = (const float*)d_in[0];
    const float* f_bonds = (const float*)d_in[1];
    const int*   a2a     = (const int*)d_in[2];
    const int*   a2b     = (const int*)d_in[3];
    const int*   mol_ids = (const int*)d_in[4];
    const int base = n_in - 16;
    const float* W_i_w  = (const float*)d_in[base + 0];
    const float* W_i_b  = (const float*)d_in[base + 1];
    const float* Wh0_w  = (const float*)d_in[base + 2];
    const float* Wh0_b  = (const float*)d_in[base + 3];
    const float* Wh1_w  = (const float*)d_in[base + 4];
    const float* Wh1_b  = (const float*)d_in[base + 5];
    const float* Wh2_w  = (const float*)d_in[base + 6];
    const float* Wh2_b  = (const float*)d_in[base + 7];
    const float* Wah0_w = (const float*)d_in[base + 8];
    const float* Wah0_b = (const float*)d_in[base + 9];
    const float* Wah1_w = (const float*)d_in[base + 10];
    const float* Wah1_b = (const float*)d_in[base + 11];
    const float* Wah2_w = (const float*)d_in[base + 12];
    const float* Wah2_b = (const float*)d_in[base + 13];
    const float* W_o_w  = (const float*)d_in[base + 14];
    const float* W_o_b  = (const float*)d_in[base + 15];

    const int M      = in_sizes[0] / 133;
    const int n_mols = out_size / DIM;

    float *p_msg, *p_t0, *p_t1, *p_gath, *p_bias;
    __nv_bfloat16* p_wt;
    cudaGetSymbolAddress((void**)&p_msg,  g_msg);
    cudaGetSymbolAddress((void**)&p_t0,   g_t0);
    cudaGetSymbolAddress((void**)&p_t1,   g_t1);
    cudaGetSymbolAddress((void**)&p_gath, g_gath);
    cudaGetSymbolAddress((void**)&p_bias, g_bias);
    cudaGetSymbolAddress((void**)&p_wt,   g_wt);

    // weight plane offsets in bf16 elements (hi plane; lo = hi + 512*Kp)
    const size_t OFF_WI   = 0;         // Kp=192
    const size_t OFF_WAH0 = 196608;    // Kp=192
    const size_t OFF_WH0  = 393216;    // Kp=512
    const size_t OFF_WH1  = 917504;
    const size_t OFF_WH2  = 1441792;
    const size_t OFF_WAH1 = 1966080;
    const size_t OFF_WAH2 = 2490368;
    const size_t OFF_WOT  = 3014656;
    const size_t OFF_WOB  = 3538944;

    const int SMEM_BYTES = 110592;
    cudaFuncSetAttribute(gemm_mma<false, true,  false>, cudaFuncAttributeMaxDynamicSharedMemorySize, SMEM_BYTES);
    cudaFuncSetAttribute(gemm_mma<true,  false, true >, cudaFuncAttributeMaxDynamicSharedMemorySize, SMEM_BYTES);
    cudaFuncSetAttribute(gemm_mma<false, true,  true >, cudaFuncAttributeMaxDynamicSharedMemorySize, SMEM_BYTES);
    cudaFuncSetAttribute(gemm_mma<false, false, true >, cudaFuncAttributeMaxDynamicSharedMemorySize, SMEM_BYTES);

    // ---- weight prep ----
    prep_weight<<<256, 256>>>(W_i_w,  p_wt + OFF_WI,   133, 192);
    prep_weight<<<256, 256>>>(Wah0_w, p_wt + OFF_WAH0, 133, 192);
    prep_weight<<<256, 256>>>(Wh0_w,  p_wt + OFF_WH0,  512, 512);
    prep_weight<<<256, 256>>>(Wh1_w,  p_wt + OFF_WH1,  512, 512);
    prep_weight<<<256, 256>>>(Wh2_w,  p_wt + OFF_WH2,  512, 512);
    prep_weight<<<256, 256>>>(Wah1_w, p_wt + OFF_WAH1, 512, 512);
    prep_weight<<<256, 256>>>(Wah2_w, p_wt + OFF_WAH2, 512, 512);
    prep_weight<<<256, 256>>>(W_o_w,                     p_wt + OFF_WOT, 512, 512);
    prep_weight<<<256, 256>>>(W_o_w + (size_t)DIM * DIM, p_wt + OFF_WOB, 512, 512);

    cudaMemsetAsync(d_out, 0, (size_t)out_size * sizeof(float), 0);

    bond_bias_kernel<<<M, 128>>>(f_bonds, a2b, Wh0_w + (size_t)DIM * DIM, Wh0_b, p_bias);

    const dim3 gg(4, (M + 127) / 128);

    // msg = relu(f_atoms @ W_i + b_i), row0 zeroed
    gemm_mma<false, true, false><<<gg, 256, SMEM_BYTES>>>(
        f_atoms, p_wt + OFF_WI, W_i_b, nullptr, p_msg, M, 133, 192, 1);

    for (int d = 0; d < 4; d++) {
        gather_sum6<<<M, 128>>>(p_msg, a2a, p_gath);
        gemm_mma<true, false, true><<<gg, 256, SMEM_BYTES>>>(
            p_gath, p_wt + OFF_WH0, nullptr, p_bias, p_t0, M, 512, 512, 0);
        gemm_mma<true, false, true><<<gg, 256, SMEM_BYTES>>>(
            p_t0, p_wt + OFF_WH1, Wh1_b, nullptr, p_t1, M, 512, 512, 0);
        gemm_mma<true, false, true><<<gg, 256, SMEM_BYTES>>>(
            p_t1, p_wt + OFF_WH2, Wh2_b, p_msg, p_msg, M, 512, 512, 1);
    }

    gather_sum6<<<M, 128>>>(p_msg, a2a, p_gath);

    // cc chain
    gemm_mma<false, true, false><<<gg, 256, SMEM_BYTES>>>(
        f_atoms, p_wt + OFF_WAH0, Wah0_b, nullptr, p_t0, M, 133, 192, 0);
    gemm_mma<false, true, true><<<gg, 256, SMEM_BYTES>>>(
        p_t0, p_wt + OFF_WAH1, Wah1_b, nullptr, p_t1, M, 512, 512, 0);
    gemm_mma<false, true, true><<<gg, 256, SMEM_BYTES>>>(
        p_t1, p_wt + OFF_WAH2, Wah2_b, nullptr, p_t0, M, 512, 512, 0);

    // out = relu(cc @ Wo_top + a_message @ Wo_bot + b_o)
    gemm_mma<false, false, true><<<gg, 256, SMEM_BYTES>>>(
        p_t0, p_wt + OFF_WOT, W_o_b, nullptr, p_t1, M, 512, 512, 0);
    gemm_mma<false, true, true><<<gg, 256, SMEM_BYTES>>>(
        p_gath, p_wt + OFF_WOB, nullptr, p_t1, p_t0, M, 512, 512, 0);

    segment_atomic<<<M, 128>>>(p_t0, mol_ids, (float*)d_out, n_mols);
}